// round 3
// baseline (speedup 1.0000x reference)
#include <cuda_runtime.h>
#include <math.h>

// ---------------------------------------------------------------------------
// Problem constants
// ---------------------------------------------------------------------------
#define BB   2
#define LL   1024
#define DD   768
#define EE   1536
#define NSTATE 16
#define RR   48
#define KCONV 4
#define NLAYER 4
#define NCLS 5
#define XDIM 80              // R + 2N
#define ROWS (BB*LL)         // 2048
#define SPLITK_X 12          // split-K factor for the N=80 GEMM

// ---------------------------------------------------------------------------
// Scratch (static device memory; allocation at runtime is forbidden)
// ---------------------------------------------------------------------------
__device__ float g_h   [ROWS*DD];        //  6.3 MB residual stream
__device__ float g_hn  [ROWS*DD];        //  6.3 MB rmsnorm output
__device__ float g_proj[ROWS*2*EE];      // 25.2 MB u_raw | gate
__device__ float g_u   [ROWS*EE];        // 12.6 MB conv+silu output
__device__ float g_xdbc[ROWS*XDIM];      //  0.7 MB
__device__ float g_xpart[SPLITK_X*ROWS*XDIM]; // 7.9 MB split-K partials
__device__ float g_dt  [ROWS*EE];        // 12.6 MB
__device__ float g_y   [ROWS*EE];        // 12.6 MB
__device__ float g_pooled[BB*DD];

// ---------------------------------------------------------------------------
// Input projection: h = x @ proj_w^T + proj_b   (x: 2048x12, proj_w: 768x12)
// ---------------------------------------------------------------------------
__global__ void k_proj(const float* __restrict__ x,
                       const float* __restrict__ w,
                       const float* __restrict__ b,
                       float* __restrict__ h)
{
    int idx = blockIdx.x * blockDim.x + threadIdx.x;
    if (idx >= ROWS * DD) return;
    int r = idx / DD, d = idx % DD;
    const float* xr = x + r * 12;
    const float* wr = w + d * 12;
    float acc = b[d];
#pragma unroll
    for (int j = 0; j < 12; j++) acc = fmaf(xr[j], wr[j], acc);
    h[idx] = acc;
}

// ---------------------------------------------------------------------------
// RMSNorm over last dim (D=768). One block per row.
// ---------------------------------------------------------------------------
__global__ void k_rms(const float* __restrict__ x,
                      const float* __restrict__ w,
                      float* __restrict__ o)
{
    int r = blockIdx.x;
    const float* xr = x + (size_t)r * DD;
    float s = 0.f;
    for (int d = threadIdx.x; d < DD; d += 256) { float v = xr[d]; s = fmaf(v, v, s); }
#pragma unroll
    for (int off = 16; off; off >>= 1) s += __shfl_xor_sync(0xffffffffu, s, off);
    __shared__ float red[8];
    __shared__ float rs_s;
    if ((threadIdx.x & 31) == 0) red[threadIdx.x >> 5] = s;
    __syncthreads();
    if (threadIdx.x < 32) {
        float t = (threadIdx.x < 8) ? red[threadIdx.x] : 0.f;
#pragma unroll
        for (int off = 4; off; off >>= 1) t += __shfl_xor_sync(0xffffffffu, t, off);
        if (threadIdx.x == 0) rs_s = rsqrtf(t / (float)DD + 1e-5f);
    }
    __syncthreads();
    float rs = rs_s;
    for (int d = threadIdx.x; d < DD; d += 256)
        o[(size_t)r * DD + d] = xr[d] * rs * w[d];
}

// ---------------------------------------------------------------------------
// Tiled FP32 GEMM (NT): C[M,N] (op)= A[M,K] * W[N,K]^T
//   A row stride = lda (K-contiguous), W row stride = K, C row stride = ldc.
//   MODE 0: C = acc
//   MODE 1: C = softplus(acc + bias[n])
//   MODE 2: C += acc          (residual accumulate, in place)
//   Split-K: gridDim.z chunks of kchunk; each z writes C + z*M*ldc (MODE 0 only).
//   Assumes M % 128 == 0 (true for all call sites: M = 2048).
// ---------------------------------------------------------------------------
template <int MODE>
__global__ __launch_bounds__(256, 2)
void gemm_nt(const float* __restrict__ A, int lda,
             const float* __restrict__ W,
             const float* __restrict__ bias,
             float* __restrict__ C, int ldc,
             int M, int N, int K, int kchunk)
{
    const int BM = 128, BN = 128, BK = 16;
    __shared__ float As[BK][BM + 4];
    __shared__ float Ws[BK][BN + 4];

    int tid = threadIdx.x;
    int tx = tid & 15, ty = tid >> 4;
    int rowA0 = blockIdx.y * BM;
    int rowW0 = blockIdx.x * BN;

    if (gridDim.z > 1) C += (size_t)blockIdx.z * (size_t)M * (size_t)ldc;
    int kb = blockIdx.z * kchunk;
    int ke = kb + kchunk;

    float acc[8][8];
#pragma unroll
    for (int i = 0; i < 8; i++)
#pragma unroll
        for (int j = 0; j < 8; j++) acc[i][j] = 0.f;

    int lrow = tid >> 2;          // 0..63
    int lcol = (tid & 3) * 4;     // 0,4,8,12

    for (int k0 = kb; k0 < ke; k0 += BK) {
#pragma unroll
        for (int jj = 0; jj < 2; jj++) {
            int r = lrow + 64 * jj;
            // A tile (rows always in range: M multiple of 128)
            const float4 va = *(const float4*)(A + (size_t)(rowA0 + r) * lda + k0 + lcol);
            As[lcol + 0][r] = va.x; As[lcol + 1][r] = va.y;
            As[lcol + 2][r] = va.z; As[lcol + 3][r] = va.w;
            // W tile (guard rows against N)
            int gw = rowW0 + r;
            float4 vw = make_float4(0.f, 0.f, 0.f, 0.f);
            if (gw < N) vw = *(const float4*)(W + (size_t)gw * K + k0 + lcol);
            Ws[lcol + 0][r] = vw.x; Ws[lcol + 1][r] = vw.y;
            Ws[lcol + 2][r] = vw.z; Ws[lcol + 3][r] = vw.w;
        }
        __syncthreads();
#pragma unroll
        for (int k = 0; k < BK; k++) {
            float a[8], b[8];
#pragma unroll
            for (int i = 0; i < 4; i++) {
                a[i]     = As[k][ty * 4 + i];
                a[i + 4] = As[k][64 + ty * 4 + i];
                b[i]     = Ws[k][tx * 4 + i];
                b[i + 4] = Ws[k][64 + tx * 4 + i];
            }
#pragma unroll
            for (int i = 0; i < 8; i++)
#pragma unroll
                for (int j = 0; j < 8; j++)
                    acc[i][j] = fmaf(a[i], b[j], acc[i][j]);
        }
        __syncthreads();
    }

#pragma unroll
    for (int i = 0; i < 8; i++) {
        int mrow = rowA0 + ((i < 4) ? (ty * 4 + i) : (64 + ty * 4 + i - 4));
#pragma unroll
        for (int j = 0; j < 8; j++) {
            int ncol = rowW0 + ((j < 4) ? (tx * 4 + j) : (64 + tx * 4 + j - 4));
            if (ncol < N) {
                float v = acc[i][j];
                float* cp = C + (size_t)mrow * ldc + ncol;
                if (MODE == 1) {
                    v += bias[ncol];
                    v = fmaxf(v, 0.f) + log1pf(__expf(-fabsf(v)));  // softplus
                }
                if (MODE == 2) v += *cp;
                *cp = v;
            }
        }
    }
}

// ---------------------------------------------------------------------------
// Reduce split-K partials for xdbc
// ---------------------------------------------------------------------------
__global__ void k_reduce_x(const float* __restrict__ part, float* __restrict__ out)
{
    int idx = blockIdx.x * blockDim.x + threadIdx.x;
    if (idx >= ROWS * XDIM) return;
    float s = 0.f;
#pragma unroll
    for (int z = 0; z < SPLITK_X; z++) s += part[(size_t)z * ROWS * XDIM + idx];
    out[idx] = s;
}

// ---------------------------------------------------------------------------
// Depthwise causal conv (K=4) + SiLU.
// Reads u_raw = proj[:, :, 0:E]; writes g_u (B,L,E)
// ---------------------------------------------------------------------------
__global__ void k_conv(const float* __restrict__ proj,
                       const float* __restrict__ cw,
                       const float* __restrict__ cb,
                       float* __restrict__ u)
{
    int idx = blockIdx.x * blockDim.x + threadIdx.x;
    if (idx >= ROWS * EE) return;
    int e = idx % EE;
    int r = idx / EE;        // b*L + t
    int t = r % LL;
    float acc = cb[e];
#pragma unroll
    for (int k = 0; k < KCONV; k++) {
        int tt = t - (KCONV - 1) + k;
        if (tt >= 0)
            acc = fmaf(cw[e * KCONV + k],
                       proj[(size_t)(r - (KCONV - 1) + k) * (2 * EE) + e], acc);
    }
    u[idx] = acc / (1.f + __expf(-acc));   // silu
}

// ---------------------------------------------------------------------------
// Selective scan. 16 lanes per (b,e) group; lane = state index n.
//   h_n <- h_n * exp(dt*A_n) + dt*B_n*u ;  y = sum_n h_n*C_n + u*Dp
//   y  <- y * silu(gate)
// ---------------------------------------------------------------------------
__global__ void k_scan(const float* __restrict__ u,
                       const float* __restrict__ dt,
                       const float* __restrict__ xdbc,
                       const float* __restrict__ A_log,
                       const float* __restrict__ Dp,
                       const float* __restrict__ proj,   // gate at [.., E + e]
                       float* __restrict__ y)
{
    int gid  = (blockIdx.x * blockDim.x + threadIdx.x) >> 4;
    int lane = threadIdx.x & 15;
    if (gid >= BB * EE) return;
    int b = gid / EE, e = gid % EE;

    float An   = -__expf(A_log[e * NSTATE + lane]);
    float dval = Dp[e];
    float h = 0.f;

    const float* dtp = dt   + (size_t)b * LL * EE + e;
    const float* up  = u    + (size_t)b * LL * EE + e;
    const float* xp  = xdbc + (size_t)b * LL * XDIM;
    const float* gp  = proj + (size_t)b * LL * 2 * EE + EE + e;
    float*       yp  = y    + (size_t)b * LL * EE + e;

    for (int t = 0; t < LL; t++) {
        float dtv = __ldg(dtp + (size_t)t * EE);
        float uv  = __ldg(up  + (size_t)t * EE);
        float Bn  = __ldg(xp + (size_t)t * XDIM + RR + lane);
        float Cn  = __ldg(xp + (size_t)t * XDIM + RR + NSTATE + lane);
        float dA  = __expf(dtv * An);
        h = fmaf(h, dA, dtv * Bn * uv);
        float yv = h * Cn;
        yv += __shfl_xor_sync(0xffffffffu, yv, 1);
        yv += __shfl_xor_sync(0xffffffffu, yv, 2);
        yv += __shfl_xor_sync(0xffffffffu, yv, 4);
        yv += __shfl_xor_sync(0xffffffffu, yv, 8);
        if (lane == 0) {
            float g  = __ldg(gp + (size_t)t * 2 * EE);
            float sg = g / (1.f + __expf(-g));
            yp[(size_t)t * EE] = (yv + uv * dval) * sg;
        }
    }
}

// ---------------------------------------------------------------------------
// Mean-pool over L (after final rmsnorm)
// ---------------------------------------------------------------------------
__global__ void k_pool(const float* __restrict__ hn, float* __restrict__ pooled)
{
    int idx = blockIdx.x * blockDim.x + threadIdx.x;
    if (idx >= BB * DD) return;
    int b = idx / DD, d = idx % DD;
    float s = 0.f;
    for (int t = 0; t < LL; t++) s += hn[(size_t)(b * LL + t) * DD + d];
    pooled[idx] = s * (1.f / (float)LL);
}

// ---------------------------------------------------------------------------
// Classifier: out[b,c] = pooled[b] . cls_w[c] + cls_b[c]    (10 outputs)
// ---------------------------------------------------------------------------
__global__ void k_cls(const float* __restrict__ pooled,
                      const float* __restrict__ w,
                      const float* __restrict__ b,
                      float* __restrict__ out)
{
    int wid  = threadIdx.x >> 5;
    int lane = threadIdx.x & 31;
    if (wid >= BB * NCLS) return;
    int bb = wid / NCLS, c = wid % NCLS;
    float s = 0.f;
    for (int d = lane; d < DD; d += 32)
        s = fmaf(pooled[bb * DD + d], w[c * DD + d], s);
#pragma unroll
    for (int off = 16; off; off >>= 1) s += __shfl_xor_sync(0xffffffffu, s, off);
    if (lane == 0) out[bb * NCLS + c] = s + b[c];
}

// ---------------------------------------------------------------------------
// kernel_launch — graph-capturable, allocation-free.
// Input order (metadata): x, proj_w, proj_b, norm_w, in_w, conv_w, conv_b,
//   xproj_w, dt_w, dt_b, A_log, D_param, out_w, fnorm_w, cls_w, cls_b
// ---------------------------------------------------------------------------
extern "C" void kernel_launch(void* const* d_in, const int* in_sizes, int n_in,
                              void* d_out, int out_size)
{
    const float* x       = (const float*)d_in[0];
    const float* proj_w  = (const float*)d_in[1];
    const float* proj_b  = (const float*)d_in[2];
    const float* norm_w  = (const float*)d_in[3];
    const float* in_w    = (const float*)d_in[4];
    const float* conv_w  = (const float*)d_in[5];
    const float* conv_b  = (const float*)d_in[6];
    const float* xproj_w = (const float*)d_in[7];
    const float* dt_w    = (const float*)d_in[8];
    const float* dt_b    = (const float*)d_in[9];
    const float* A_log   = (const float*)d_in[10];
    const float* D_param = (const float*)d_in[11];
    const float* out_w   = (const float*)d_in[12];
    const float* fnorm_w = (const float*)d_in[13];
    const float* cls_w   = (const float*)d_in[14];
    const float* cls_b   = (const float*)d_in[15];
    float* out = (float*)d_out;

    float *h_, *hn_, *proj_, *u_, *xdbc_, *xpart_, *dt_, *y_, *pooled_;
    cudaGetSymbolAddress((void**)&h_,      g_h);
    cudaGetSymbolAddress((void**)&hn_,     g_hn);
    cudaGetSymbolAddress((void**)&proj_,   g_proj);
    cudaGetSymbolAddress((void**)&u_,      g_u);
    cudaGetSymbolAddress((void**)&xdbc_,   g_xdbc);
    cudaGetSymbolAddress((void**)&xpart_,  g_xpart);
    cudaGetSymbolAddress((void**)&dt_,     g_dt);
    cudaGetSymbolAddress((void**)&y_,      g_y);
    cudaGetSymbolAddress((void**)&pooled_, g_pooled);

    // h = x @ proj_w^T + proj_b
    k_proj<<<(ROWS * DD + 255) / 256, 256>>>(x, proj_w, proj_b, h_);

    for (int i = 0; i < NLAYER; i++) {
        // hn = rmsnorm(h, norm_w[i])
        k_rms<<<ROWS, 256>>>(h_, norm_w + i * DD, hn_);

        // proj = hn @ in_w[i]^T  (2048 x 3072, K=768)
        {
            dim3 g(2 * EE / 128, ROWS / 128);
            gemm_nt<0><<<g, 256>>>(hn_, DD, in_w + (size_t)i * 2 * EE * DD,
                                   nullptr, proj_, 2 * EE,
                                   ROWS, 2 * EE, DD, DD);
        }

        // u = silu(causal_conv(proj[:,:,:E]))
        k_conv<<<(ROWS * EE + 255) / 256, 256>>>(proj_, conv_w + i * EE * KCONV,
                                                 conv_b + i * EE, u_);

        // xdbc = u @ xproj_w[i]^T  (2048 x 80, K=1536) — split-K x12
        {
            dim3 g(1, ROWS / 128, SPLITK_X);
            gemm_nt<0><<<g, 256>>>(u_, EE, xproj_w + (size_t)i * XDIM * EE,
                                   nullptr, xpart_, XDIM,
                                   ROWS, XDIM, EE, EE / SPLITK_X);
            k_reduce_x<<<(ROWS * XDIM + 255) / 256, 256>>>(xpart_, xdbc_);
        }

        // dt = softplus(xdbc[:,:,:R] @ dt_w[i]^T + dt_b[i])  (2048 x 1536, K=48)
        {
            dim3 g(EE / 128, ROWS / 128);
            gemm_nt<1><<<g, 256>>>(xdbc_, XDIM, dt_w + (size_t)i * EE * RR,
                                   dt_b + i * EE, dt_, EE,
                                   ROWS, EE, RR, RR);
        }

        // selective scan (+ D skip + gate silu)
        k_scan<<<(BB * EE * 16) / 256, 256>>>(u_, dt_, xdbc_,
                                              A_log + i * EE * NSTATE,
                                              D_param + i * EE, proj_, y_);

        // h = h + y @ out_w[i]^T  (2048 x 768, K=1536), residual in place
        {
            dim3 g(DD / 128, ROWS / 128);
            gemm_nt<2><<<g, 256>>>(y_, EE, out_w + (size_t)i * DD * EE,
                                   nullptr, h_, DD,
                                   ROWS, DD, EE, EE);
        }
    }

    // final rmsnorm, mean pool, classifier
    k_rms<<<ROWS, 256>>>(h_, fnorm_w, hn_);
    k_pool<<<(BB * DD + 255) / 256, 256>>>(hn_, pooled_);
    k_cls<<<1, 320>>>(pooled_, cls_w, cls_b, out);
}